// round 13
// baseline (speedup 1.0000x reference)
#include <cuda_runtime.h>
#include <cuda_bf16.h>

// -------- constants from the reference --------
#define POOL_SIZE   32
#define PROMPT_LEN  32
#define NCTX        32
#define EMBED       768
#define TOP_K       5
#define N_CLS       1000
#define SUFFIX_LEN  12
#define EMBED_F4    (EMBED / 4)          // 192
#define CLS_F4      14784u               // 77*192
#define PROMPTS_F4  14784000u            // 1000*14784
#define SUF_F4      2304u                // 12*192

// kC_rest flat space: 1000 classes x 13 rows (prefix+suffix) + pool/key
#define ROWS13_F4    2496u               // 13*192
#define NR_PROMPT    2496000u            // 1000*2496
#define NR_TOTAL     2698752u            // + 196608 + 6144

// -------- device scratch (zero-init at load) --------
__device__ float4 g_combined4[PROMPT_LEN * EMBED_F4];

// ============================================================
// kSel: 32 independent blocks x 256 threads, NO inter-block sync.
// Block b: prefetch candidate pool rows, redundantly compute all 32
// sims, top-5, gates + weighted sum for token position b.
// ============================================================
__global__ __launch_bounds__(256, 1)
void kSel(const float4* __restrict__ x4,       // [16,192]
          const float4* __restrict__ key4,     // [32,192]
          const float4* __restrict__ pool4,    // [32,32,192]
          const float4* __restrict__ aw4,      // [192]
          const float*  __restrict__ ab)       // [1]
{
    __shared__ float4 qs4[EMBED_F4];
    __shared__ float  sims[POOL_SIZE];
    __shared__ int    idxs[TOP_K];
    __shared__ float  part[6][TOP_K];
    __shared__ float  wt_s[TOP_K];

    const int t = threadIdx.x;
    const int w = t >> 5, lane = t & 31;
    const int b = blockIdx.x;                  // token position

    // L2-prefetch the 32 candidate pool rows for position b
    for (int i = t; i < 32 * 24; i += 256) {
        const int p = i / 24, line = i - p * 24;
        const float4* addr = pool4 + (p * PROMPT_LEN + b) * EMBED_F4 + line * 8;
        asm volatile("prefetch.global.L2 [%0];" :: "l"(addr));
    }

    // q = sum over 16 frames (mean scale & q-norm don't affect top-k)
    if (t < EMBED_F4) {
        float4 s = make_float4(0.f, 0.f, 0.f, 0.f);
        #pragma unroll
        for (int f = 0; f < 16; ++f) {
            float4 v = __ldg(&x4[f * EMBED_F4 + t]);
            s.x += v.x; s.y += v.y; s.z += v.z; s.w += v.w;
        }
        qs4[t] = s;
    }
    __syncthreads();

    // all 32 sims, redundantly per block: 8 warps x 4 keys
    #pragma unroll
    for (int j = 0; j < 4; ++j) {
        const int p = w + 8 * j;
        const float4* kp = key4 + p * EMBED_F4;
        float dot = 0.f, nrm = 0.f;
        #pragma unroll
        for (int i = 0; i < 6; ++i) {
            const int c = lane + i * 32;
            float4 kv = __ldg(&kp[c]), qv = qs4[c];
            dot += kv.x*qv.x + kv.y*qv.y + kv.z*qv.z + kv.w*qv.w;
            nrm += kv.x*kv.x + kv.y*kv.y + kv.z*kv.z + kv.w*kv.w;
        }
        #pragma unroll
        for (int o = 16; o; o >>= 1) {
            dot += __shfl_down_sync(0xffffffffu, dot, o);
            nrm += __shfl_down_sync(0xffffffffu, nrm, o);
        }
        if (lane == 0) sims[p] = dot * rsqrtf(nrm);
    }
    __syncthreads();

    // top-5, strict '>' = lowest index wins ties (matches jax.lax.top_k)
    if (t == 0) {
        unsigned usedmask = 0u;
        for (int k = 0; k < TOP_K; ++k) {
            int best = 0; float bv = -3.0e38f;
            #pragma unroll
            for (int p = 0; p < POOL_SIZE; ++p)
                if (!((usedmask >> p) & 1u) && sims[p] > bv) { bv = sims[p]; best = p; }
            usedmask |= 1u << best;
            idxs[k] = best;
        }
    }
    __syncthreads();

    // gates + weighted sum for token position b (first 192 threads)
    if (t < EMBED_F4) {
        const float4* rows[TOP_K];
        #pragma unroll
        for (int k = 0; k < TOP_K; ++k)
            rows[k] = pool4 + (idxs[k] * PROMPT_LEN + b) * EMBED_F4;

        float4 av = __ldg(&aw4[t]);
        float4 rv[TOP_K];
        float dots[TOP_K];
        #pragma unroll
        for (int k = 0; k < TOP_K; ++k) {
            rv[k] = __ldg(&rows[k][t]);          // L2 hit (prefetched)
            dots[k] = rv[k].x*av.x + rv[k].y*av.y + rv[k].z*av.z + rv[k].w*av.w;
        }
        #pragma unroll
        for (int k = 0; k < TOP_K; ++k) {
            #pragma unroll
            for (int o = 16; o; o >>= 1)
                dots[k] += __shfl_down_sync(0xffffffffu, dots[k], o);
        }
        if (lane == 0) {
            #pragma unroll
            for (int k = 0; k < TOP_K; ++k) part[w][k] = dots[k];
        }
        __syncthreads();
        if (t < TOP_K) {
            float d = 0.f;
            #pragma unroll
            for (int i = 0; i < 6; ++i) d += part[i][t];
            wt_s[t] = 1.f / (1.f + __expf(-(d + ab[0])));
        }
        __syncthreads();

        float4 acc = make_float4(0.f, 0.f, 0.f, 0.f);
        #pragma unroll
        for (int k = 0; k < TOP_K; ++k) {
            const float wk = wt_s[k];
            acc.x += wk*rv[k].x; acc.y += wk*rv[k].y;
            acc.z += wk*rv[k].z; acc.w += wk*rv[k].w;
        }
        g_combined4[b * EMBED_F4 + t] = acc;
    } else {
        __syncthreads();
        __syncthreads();
    }
}

// ============================================================
// kC_rest: prefix + suffix + pool/key (pure streams, ~84 MB)
// ============================================================
__global__ void kC_rest(const float4* __restrict__ pre4,
                        const float4* __restrict__ suf4,
                        const float4* __restrict__ pol4,
                        const float4* __restrict__ key4,
                        float4* __restrict__ out)
{
    unsigned idx = blockIdx.x * blockDim.x + threadIdx.x;
    const unsigned stride = gridDim.x * blockDim.x;

    for (; idx < NR_TOTAL; idx += stride) {
        float4 v;
        unsigned o;
        if (idx < NR_PROMPT) {
            const unsigned c   = idx / ROWS13_F4;        // magic-multiply
            const unsigned rem = idx - c * ROWS13_F4;
            const unsigned r   = rem / EMBED_F4;
            const unsigned col = rem - r * EMBED_F4;
            if (r == 0u) {
                v = __ldcs(&pre4[c * EMBED_F4 + col]);
                o = c * CLS_F4 + col;
            } else {
                v = __ldcs(&suf4[c * SUF_F4 + (r - 1u) * EMBED_F4 + col]);
                o = c * CLS_F4 + (64u + r) * EMBED_F4 + col;   // rows 65..76
            }
        } else {
            const unsigned q = idx - NR_PROMPT;          // pool then key
            v = (q < 196608u) ? __ldcs(&pol4[q]) : __ldcs(&key4[q - 196608u]);
            o = PROMPTS_F4 + q;
        }
        __stcs(&out[o], v);
    }
}

// ============================================================
// kC_ctx: ctx rows 33..64 broadcast. 800 blocks = 8 rowgroups x 100
// classgroups; each thread holds 3 f4 in registers, stores to 10 classes.
// ============================================================
__global__ __launch_bounds__(256, 8)
void kC_ctx(const float4* __restrict__ ctx4, float4* __restrict__ out)
{
    const unsigned b  = blockIdx.x;
    const unsigned rg = b & 7u;           // row group (4 rows each)
    const unsigned cg = b >> 3;           // class group (10 classes each)
    const unsigned t  = threadIdx.x;

    const unsigned src_off = rg * 4u * EMBED_F4;     // contiguous 768 f4
    const float4 v0 = __ldg(&ctx4[src_off + t]);
    const float4 v1 = __ldg(&ctx4[src_off + t + 256u]);
    const float4 v2 = __ldg(&ctx4[src_off + t + 512u]);

    #pragma unroll
    for (unsigned cc = 0; cc < 10u; ++cc) {
        const unsigned c = cg * 10u + cc;
        float4* dst = out + c * CLS_F4 + (33u + rg * 4u) * EMBED_F4;
        __stcs(&dst[t],         v0);
        __stcs(&dst[t + 256u],  v1);
        __stcs(&dst[t + 512u],  v2);
    }
}

// ============================================================
// kC_cmb: combined rows 1..32 broadcast, same register-tile scheme
// ============================================================
__global__ __launch_bounds__(256, 8)
void kC_cmb(float4* __restrict__ out)
{
    const unsigned b  = blockIdx.x;
    const unsigned rg = b & 7u;
    const unsigned cg = b >> 3;
    const unsigned t  = threadIdx.x;

    const unsigned src_off = rg * 4u * EMBED_F4;
    const float4 v0 = __ldg(&g_combined4[src_off + t]);
    const float4 v1 = __ldg(&g_combined4[src_off + t + 256u]);
    const float4 v2 = __ldg(&g_combined4[src_off + t + 512u]);

    #pragma unroll
    for (unsigned cc = 0; cc < 10u; ++cc) {
        const unsigned c = cg * 10u + cc;
        float4* dst = out + c * CLS_F4 + (1u + rg * 4u) * EMBED_F4;
        __stcs(&dst[t],         v0);
        __stcs(&dst[t + 256u],  v1);
        __stcs(&dst[t + 512u],  v2);
    }
}

// ============================================================
extern "C" void kernel_launch(void* const* d_in, const int* in_sizes, int n_in,
                              void* d_out, int out_size)
{
    const float* x_embed      = (const float*)d_in[0];
    const float* prompt_pool  = (const float*)d_in[1];
    const float* prompt_key   = (const float*)d_in[2];
    const float* alpha_w      = (const float*)d_in[3];
    const float* alpha_b      = (const float*)d_in[4];
    const float* ctx          = (const float*)d_in[5];
    const float* token_prefix = (const float*)d_in[6];
    const float* token_suffix = (const float*)d_in[7];
    // d_in[8] = train_flag: the penalty is a positive scalar on sims ->
    // top-k ordering (and therefore the output) is unchanged; safely ignored.

    // Side stream + fork/join events, created once on the first (non-capture)
    // correctness call. No device memory is allocated.
    static cudaStream_t s1;
    static cudaEvent_t  eFork, eJoin;
    static int init = 0;
    if (!init) {
        cudaStreamCreateWithFlags(&s1, cudaStreamNonBlocking);
        cudaEventCreateWithFlags(&eFork, cudaEventDisableTiming);
        cudaEventCreateWithFlags(&eJoin, cudaEventDisableTiming);
        init = 1;
    }

    // fork
    cudaEventRecord(eFork, 0);
    cudaStreamWaitEvent(s1, eFork, 0);

    // branch 1 (side): selection, then combined broadcast (96 MB)
    kSel<<<POOL_SIZE, 256, 0, s1>>>((const float4*)x_embed,
                                    (const float4*)prompt_key,
                                    (const float4*)prompt_pool,
                                    (const float4*)alpha_w, alpha_b);
    kC_cmb<<<800, 256, 0, s1>>>((float4*)d_out);

    // branch 0 (main): streams (84 MB), then ctx broadcast (96 MB)
    kC_rest<<<1320, 256>>>((const float4*)token_prefix,
                           (const float4*)token_suffix,
                           (const float4*)prompt_pool,
                           (const float4*)prompt_key,
                           (float4*)d_out);
    kC_ctx<<<800, 256>>>((const float4*)ctx, (float4*)d_out);

    // join
    cudaEventRecord(eJoin, s1);
    cudaStreamWaitEvent(0, eJoin, 0);
}

// round 14
// speedup vs baseline: 1.0393x; 1.0393x over previous
#include <cuda_runtime.h>
#include <cuda_bf16.h>

// -------- constants from the reference --------
#define POOL_SIZE   32
#define PROMPT_LEN  32
#define NCTX        32
#define EMBED       768
#define TOP_K       5
#define N_CLS       1000
#define SUFFIX_LEN  12
#define EMBED_F4    (EMBED / 4)          // 192
#define CLS_F4      14784u               // 77*192
#define PROMPTS_F4  14784000u            // 1000*14784
#define SUF_F4      2304u                // 12*192

// Region A flat f4 space (selection-independent):
//   1000 classes x 45 rows (prefix,ctx,suffix) = 8,640,000  + pool/key 202,752
#define NA_PROMPT   8640000u
#define NA_TOTAL    8842752u             // = 1536 * 5757 exactly
#define ROWS45_F4   8640u                // 45*192
// Region B flat f4 space (combined broadcast): 1000 x 32 x 192
#define NB_TOTAL    6144000u             // = 1536 * 4000 exactly
#define CMBCLS_F4   6144u                // 32*192

#define SEL_BLOCKS  32u
#define A_BLOCKS    5757u                // 1536 f4 per block
#define B_BLOCKS    4000u
#define GRID_TOTAL  (SEL_BLOCKS + A_BLOCKS + B_BLOCKS)   // 9789
#define TILE_F4     1536u                // 256 threads x 6 f4

// -------- device scratch / sync (zero-init at load) --------
__device__ float4   g_combined4[PROMPT_LEN * EMBED_F4];
__device__ unsigned g_selctr;    // selection blocks completed
__device__ int      g_flag;      // combined ready
__device__ unsigned g_doneB;     // B blocks completed (for replay reset)

// ============================================================
__global__ __launch_bounds__(256, 6)
void k_all(const float4* __restrict__ x4,       // [16,192]
           const float4* __restrict__ key4,     // [32,192]
           const float4* __restrict__ pool4,    // [32,32,192]
           const float4* __restrict__ aw4,      // [192]
           const float*  __restrict__ ab,       // [1]
           const float4* __restrict__ pre4,     // [1000,192]
           const float4* __restrict__ suf4,     // [1000,12,192]
           const float4* __restrict__ ctx4,     // [32,192]
           float4* __restrict__ out)
{
    const unsigned bid = blockIdx.x;
    const int t = threadIdx.x;

    // ========================================================
    // blocks 0..31: selection + gating for token position bid.
    // Guaranteed wave-1 resident (lowest block indices).
    // ========================================================
    if (bid < SEL_BLOCKS) {
        __shared__ float4 qs4[EMBED_F4];
        __shared__ float  sims[POOL_SIZE];
        __shared__ int    idxs[TOP_K];
        __shared__ float  part[6][TOP_K];
        __shared__ float  wt_s[TOP_K];

        const int w = t >> 5, lane = t & 31;
        const int b = (int)bid;                // token position

        // L2-prefetch the 32 candidate pool rows for position b
        for (int i = t; i < 32 * 24; i += 256) {
            const int p = i / 24, line = i - p * 24;
            const float4* addr = pool4 + (p * PROMPT_LEN + b) * EMBED_F4 + line * 8;
            asm volatile("prefetch.global.L2 [%0];" :: "l"(addr));
        }

        // q = sum over 16 frames (mean scale & q-norm don't affect top-k)
        if (t < EMBED_F4) {
            float4 s = make_float4(0.f, 0.f, 0.f, 0.f);
            #pragma unroll
            for (int f = 0; f < 16; ++f) {
                float4 v = __ldg(&x4[f * EMBED_F4 + t]);
                s.x += v.x; s.y += v.y; s.z += v.z; s.w += v.w;
            }
            qs4[t] = s;
        }
        __syncthreads();

        // all 32 sims, redundantly per block: 8 warps x 4 keys
        // sim = (k.q)/||k||  (order-equivalent to cosine similarity)
        #pragma unroll
        for (int j = 0; j < 4; ++j) {
            const int p = w + 8 * j;
            const float4* kp = key4 + p * EMBED_F4;
            float dot = 0.f, nrm = 0.f;
            #pragma unroll
            for (int i = 0; i < 6; ++i) {
                const int c = lane + i * 32;
                float4 kv = __ldg(&kp[c]), qv = qs4[c];
                dot += kv.x*qv.x + kv.y*qv.y + kv.z*qv.z + kv.w*qv.w;
                nrm += kv.x*kv.x + kv.y*kv.y + kv.z*kv.z + kv.w*kv.w;
            }
            #pragma unroll
            for (int o = 16; o; o >>= 1) {
                dot += __shfl_down_sync(0xffffffffu, dot, o);
                nrm += __shfl_down_sync(0xffffffffu, nrm, o);
            }
            if (lane == 0) sims[p] = dot * rsqrtf(nrm);
        }
        __syncthreads();

        // top-5, strict '>' = lowest index wins ties (matches jax.lax.top_k)
        if (t == 0) {
            unsigned usedmask = 0u;
            for (int k = 0; k < TOP_K; ++k) {
                int best = 0; float bv = -3.0e38f;
                #pragma unroll
                for (int p = 0; p < POOL_SIZE; ++p)
                    if (!((usedmask >> p) & 1u) && sims[p] > bv) { bv = sims[p]; best = p; }
                usedmask |= 1u << best;
                idxs[k] = best;
            }
        }
        __syncthreads();

        // gates + weighted sum for token position b (first 192 threads)
        if (t < EMBED_F4) {
            const float4* rows[TOP_K];
            #pragma unroll
            for (int k = 0; k < TOP_K; ++k)
                rows[k] = pool4 + (idxs[k] * PROMPT_LEN + b) * EMBED_F4;

            float4 av = __ldg(&aw4[t]);
            float dots[TOP_K];
            #pragma unroll
            for (int k = 0; k < TOP_K; ++k) {
                float4 rv = __ldg(&rows[k][t]);          // L2 hit (prefetched)
                dots[k] = rv.x*av.x + rv.y*av.y + rv.z*av.z + rv.w*av.w;
            }
            #pragma unroll
            for (int k = 0; k < TOP_K; ++k) {
                #pragma unroll
                for (int o = 16; o; o >>= 1)
                    dots[k] += __shfl_down_sync(0xffffffffu, dots[k], o);
            }
            if (lane == 0) {
                #pragma unroll
                for (int k = 0; k < TOP_K; ++k) part[w][k] = dots[k];
            }
            __syncthreads();
            if (t < TOP_K) {
                float d = 0.f;
                #pragma unroll
                for (int i = 0; i < 6; ++i) d += part[i][t];
                wt_s[t] = 1.f / (1.f + __expf(-(d + ab[0])));
            }
            __syncthreads();

            float4 acc = make_float4(0.f, 0.f, 0.f, 0.f);
            #pragma unroll
            for (int k = 0; k < TOP_K; ++k) {
                const float wk = wt_s[k];
                float4 rv = __ldg(&rows[k][t]);          // L1 hit (just read)
                acc.x += wk*rv.x; acc.y += wk*rv.y;
                acc.z += wk*rv.z; acc.w += wk*rv.w;
            }
            g_combined4[b * EMBED_F4 + t] = acc;
        } else {
            __syncthreads();
            __syncthreads();
        }

        // publish: last selection block sets the flag
        __syncthreads();
        if (t == 0) {
            __threadfence();
            unsigned prev = atomicAdd(&g_selctr, 1u);
            if (prev == SEL_BLOCKS - 1u) atomicExch(&g_flag, 1);
        }
        return;
    }

    // ========================================================
    // blocks 32..5788: region A tile (prefix/ctx/suffix/pool/key)
    // ========================================================
    if (bid < SEL_BLOCKS + A_BLOCKS) {
        const unsigned base = (bid - SEL_BLOCKS) * TILE_F4 + (unsigned)t;
        #pragma unroll
        for (int i = 0; i < 6; ++i) {
            const unsigned idx = base + (unsigned)i * 256u;
            float4 v;
            unsigned o;
            if (idx < NA_PROMPT) {
                const unsigned c   = idx / ROWS45_F4;        // magic-multiply
                const unsigned rem = idx - c * ROWS45_F4;
                const unsigned r   = rem / EMBED_F4;
                const unsigned col = rem - r * EMBED_F4;
                if (r == 0u) {
                    v = __ldcs(&pre4[c * EMBED_F4 + col]);
                    o = c * CLS_F4 + col;
                } else if (r <= 32u) {
                    v = __ldg(&ctx4[(r - 1u) * EMBED_F4 + col]);   // reused 1000x
                    o = c * CLS_F4 + (r + 32u) * EMBED_F4 + col;
                } else {
                    v = __ldcs(&suf4[c * SUF_F4 + (r - 33u) * EMBED_F4 + col]);
                    o = c * CLS_F4 + (r + 32u) * EMBED_F4 + col;
                }
            } else {
                const unsigned q = idx - NA_PROMPT;          // pool then key
                v = (q < 196608u) ? __ldcs(&pool4[q]) : __ldcs(&key4[q - 196608u]);
                o = PROMPTS_F4 + q;
            }
            __stcs(&out[o], v);
        }
        return;
    }

    // ========================================================
    // blocks 5789..9788: region B tile (combined broadcast).
    // These become resident only after thousands of A-block
    // retirements -> the flag is long set; the spin is free.
    // ========================================================
    {
        if (t == 0) {
            while (atomicAdd(&g_flag, 0) == 0) __nanosleep(128);
        }
        __syncthreads();
        __threadfence();

        const unsigned base = (bid - SEL_BLOCKS - A_BLOCKS) * TILE_F4 + (unsigned)t;
        #pragma unroll
        for (int i = 0; i < 6; ++i) {
            const unsigned idx = base + (unsigned)i * 256u;
            const unsigned c   = idx / CMBCLS_F4;            // magic-multiply
            const unsigned rem = idx - c * CMBCLS_F4;
            __stcs(&out[c * CLS_F4 + EMBED_F4 + rem], __ldg(&g_combined4[rem]));
        }

        // replay reset: last B block zeroes all sync state
        __syncthreads();
        if (t == 0) {
            __threadfence();
            unsigned prev = atomicAdd(&g_doneB, 1u);
            if (prev == B_BLOCKS - 1u) {
                g_doneB = 0u; g_selctr = 0u; g_flag = 0;
            }
        }
    }
}

// ============================================================
extern "C" void kernel_launch(void* const* d_in, const int* in_sizes, int n_in,
                              void* d_out, int out_size)
{
    const float* x_embed      = (const float*)d_in[0];
    const float* prompt_pool  = (const float*)d_in[1];
    const float* prompt_key   = (const float*)d_in[2];
    const float* alpha_w      = (const float*)d_in[3];
    const float* alpha_b      = (const float*)d_in[4];
    const float* ctx          = (const float*)d_in[5];
    const float* token_prefix = (const float*)d_in[6];
    const float* token_suffix = (const float*)d_in[7];
    // d_in[8] = train_flag: the penalty is a positive scalar on sims ->
    // top-k ordering (and therefore the output) is unchanged; safely ignored.

    k_all<<<GRID_TOTAL, 256>>>((const float4*)x_embed,
                               (const float4*)prompt_key,
                               (const float4*)prompt_pool,
                               (const float4*)alpha_w,
                               alpha_b,
                               (const float4*)token_prefix,
                               (const float4*)token_suffix,
                               (const float4*)ctx,
                               (float4*)d_out);
}